// round 9
// baseline (speedup 1.0000x reference)
#include <cuda_runtime.h>
#include <cstdint>

// ---------------- problem constants ----------------
#define BATCH   32
#define NTOK    1024
#define DDIM    1024
#define MFF     4096
#define LN_EPS  1e-5f

#define MS_SPLIT 16
#define F1_SPLIT 16
#define F2_SPLIT 64

// ---------------- scratch ----------------
__device__ float g_x    [BATCH * NTOK];
__device__ float g_qstat[64];                 // (mean, rstd) per Q row
__device__ float g_xraw [64];                 // (sum, sumsq) per x row (atomics)
__device__ float g_part [4194304];            // split-K partials (16 MB)

#define MU_OFF  0                             // 16*32*1024 = 524288
#define SIG_OFF 524288
#define W1_OFF  0                             // 16*32*4096 = 2097152 (reuses mu/sig)
#define W2_OFF  2097152                       // 64*32*1024 = 2097152

// dynamic smem: A panel [64][68] + W panel [64][132]
#define GEMM_SMEM ((64 * 68 + 64 * 132) * 4)  // 51200 B -> 4 blocks/SM

// =====================================================================
// Q row stats (mean, rstd) + zero the x-stat accumulators. 1 block.
// =====================================================================
__global__ void stats_kernel(const float* __restrict__ Q)
{
    const int tid = threadIdx.x;
    if (tid < 64) g_xraw[tid] = 0.f;
    const int r = tid >> 5, lane = tid & 31;
    const float4* p = reinterpret_cast<const float4*>(Q + r * NTOK);
    float s = 0.f, ss = 0.f;
    #pragma unroll
    for (int i = 0; i < 8; ++i) {
        float4 v = p[lane + 32 * i];
        s  += v.x + v.y + v.z + v.w;
        ss += v.x*v.x + v.y*v.y + v.z*v.z + v.w*v.w;
    }
    #pragma unroll
    for (int o = 16; o; o >>= 1) {
        s  += __shfl_xor_sync(0xffffffffu, s,  o);
        ss += __shfl_xor_sync(0xffffffffu, ss, o);
    }
    if (lane == 0) {
        const float mean = s * (1.0f / NTOK);
        const float var  = ss * (1.0f / NTOK) - mean * mean;
        g_qstat[2 * r]     = mean;
        g_qstat[2 * r + 1] = rsqrtf(var + LN_EPS);
    }
}

// =====================================================================
// Split-K GEMM. Block tile 32(M) x 128(N); K strip 64; 256 threads;
// thread tile 4m x 4n. 51.2 KB smem + <=64 regs -> 4 blocks/SM (32
// warps, occ 50%). W loads coalesced (nL=4); transposed store with XOR
// swizzle col = n ^ ((kq&7)<<2). Inner loop (no syncs): 1 LDS.128 (W) +
// 2 broadcast LDS.128 (dup A) + 8 fma.f32x2 per kk.
// AMODE 0: A = LN(Q) (g_qstat)  1: A = LN(g_x) (g_xraw)
// AMODE 2: A = silu(sum of F1_SPLIT partials + b1)
// gridDim = (N/128, nsplit, nz); z selects W0/W1 (mu/sigma fusion).
// =====================================================================
template<int AMODE>
__global__ __launch_bounds__(256, 4)
void gemm_kernel(const float* __restrict__ W0, const float* __restrict__ W1,
                 int ldw, int N, int partOff, int partStrideZ,
                 const float* __restrict__ Ain,
                 const float* __restrict__ lng, const float* __restrict__ lnb,
                 const float* __restrict__ b1)
{
    extern __shared__ __align__(16) float smem[];
    float* a_s = smem;                  // [64][68] dup A
    float* w_s = smem + 64 * 68;        // [64][132] W, XOR-swizzled columns

    const int tid = threadIdx.x;
    const float* __restrict__ W = (blockIdx.z == 0) ? W0 : W1;
    float* __restrict__ P = g_part + partOff + (size_t)blockIdx.z * partStrideZ;

    const int j0    = blockIdx.x * 128;
    const int split = blockIdx.y;
    const int kOff  = split * 64;

    // ---- coalesced W strip load: 8 LDG.128, nL=4 each, MLP=8 ----
    float4 wv[8];
    #pragma unroll
    for (int j = 0; j < 8; ++j) {
        const int idx = j * 256 + tid;
        const int n   = idx >> 4;            // 0..127
        const int kq  = idx & 15;            // k-quad 0..15
        wv[j] = *reinterpret_cast<const float4*>(
            W + (size_t)(j0 + n) * ldw + kOff + kq * 4);
    }

    // ---- build A panel (whole 64-k strip), all 256 threads ----
    const int ra = tid >> 3;                 // row 0..31
    float mean = 0.f, rs = 0.f;
    if (AMODE == 0) { mean = g_qstat[2 * ra]; rs = g_qstat[2 * ra + 1]; }
    if (AMODE == 1) {
        const float s  = g_xraw[2 * ra];
        const float ss = g_xraw[2 * ra + 1];
        mean = s * (1.0f / NTOK);
        rs   = rsqrtf(ss * (1.0f / NTOK) - mean * mean + LN_EPS);
    }
    const float* Arow = (AMODE == 1) ? (g_x + ra * NTOK)
                      : (AMODE == 0) ? (Ain + ra * NTOK) : nullptr;

    #pragma unroll
    for (int h = 0; h < 2; ++h) {
        const int klocal = ((tid & 7) + 8 * h) * 4;
        const int kc     = kOff + klocal;
        float av[4];
        if (AMODE < 2) {
            const float4 fa = *reinterpret_cast<const float4*>(Arow + kc);
            const float4 fg = *reinterpret_cast<const float4*>(lng + kc);
            const float4 fb = *reinterpret_cast<const float4*>(lnb + kc);
            av[0] = (fa.x - mean) * rs * fg.x + fb.x;
            av[1] = (fa.y - mean) * rs * fg.y + fb.y;
            av[2] = (fa.z - mean) * rs * fg.z + fb.z;
            av[3] = (fa.w - mean) * rs * fg.w + fb.w;
        } else {
            float4 v = *reinterpret_cast<const float4*>(b1 + kc);
            #pragma unroll
            for (int s = 0; s < F1_SPLIT; ++s) {
                const float4 p = *reinterpret_cast<const float4*>(
                    g_part + W1_OFF + (size_t)(s * BATCH + ra) * MFF + kc);
                v.x += p.x; v.y += p.y; v.z += p.z; v.w += p.w;
            }
            av[0] = v.x / (1.0f + __expf(-v.x));
            av[1] = v.y / (1.0f + __expf(-v.y));
            av[2] = v.z / (1.0f + __expf(-v.z));
            av[3] = v.w / (1.0f + __expf(-v.w));
        }
        #pragma unroll
        for (int j = 0; j < 4; ++j)
            *reinterpret_cast<float2*>(&a_s[(klocal + j) * 68 + 2 * ra]) =
                make_float2(av[j], av[j]);
    }

    // ---- transposed + swizzled W store ----
    #pragma unroll
    for (int j = 0; j < 8; ++j) {
        const int idx = j * 256 + tid;
        const int n   = idx >> 4;
        const int kq  = idx & 15;
        const int col = n ^ ((kq & 7) << 2);
        w_s[(kq * 4 + 0) * 132 + col] = wv[j].x;
        w_s[(kq * 4 + 1) * 132 + col] = wv[j].y;
        w_s[(kq * 4 + 2) * 132 + col] = wv[j].z;
        w_s[(kq * 4 + 3) * 132 + col] = wv[j].w;
    }
    __syncthreads();

    // ---- main loop: 64 kk, no syncs ----
    const int tx = tid & 31, ty = tid >> 5;     // 4n per tx, 4m per ty
    const float* ap = a_s + 8 * ty;

    unsigned long long acc[4][2];
    #pragma unroll
    for (int r = 0; r < 4; ++r) { acc[r][0] = 0ull; acc[r][1] = 0ull; }

    #pragma unroll
    for (int kq2 = 0; kq2 < 16; ++kq2) {
        const float* wcol = w_s + ((4 * tx) ^ ((kq2 & 7) << 2));
        #pragma unroll
        for (int j2 = 0; j2 < 4; ++j2) {
            const int kk = kq2 * 4 + j2;
            const ulonglong2 w =
                *reinterpret_cast<const ulonglong2*>(wcol + kk * 132);
            const ulonglong2 a0 =
                *reinterpret_cast<const ulonglong2*>(ap + kk * 68);
            const ulonglong2 a1 =
                *reinterpret_cast<const ulonglong2*>(ap + kk * 68 + 4);
            asm("fma.rn.f32x2 %0, %1, %2, %0;" : "+l"(acc[0][0]) : "l"(a0.x), "l"(w.x));
            asm("fma.rn.f32x2 %0, %1, %2, %0;" : "+l"(acc[0][1]) : "l"(a0.x), "l"(w.y));
            asm("fma.rn.f32x2 %0, %1, %2, %0;" : "+l"(acc[1][0]) : "l"(a0.y), "l"(w.x));
            asm("fma.rn.f32x2 %0, %1, %2, %0;" : "+l"(acc[1][1]) : "l"(a0.y), "l"(w.y));
            asm("fma.rn.f32x2 %0, %1, %2, %0;" : "+l"(acc[2][0]) : "l"(a1.x), "l"(w.x));
            asm("fma.rn.f32x2 %0, %1, %2, %0;" : "+l"(acc[2][1]) : "l"(a1.x), "l"(w.y));
            asm("fma.rn.f32x2 %0, %1, %2, %0;" : "+l"(acc[3][0]) : "l"(a1.y), "l"(w.x));
            asm("fma.rn.f32x2 %0, %1, %2, %0;" : "+l"(acc[3][1]) : "l"(a1.y), "l"(w.y));
        }
    }

    // ---- epilogue: rows 4ty..4ty+3, cols j0+4tx..j0+4tx+3 ----
    #pragma unroll
    for (int r = 0; r < 4; ++r) {
        float f0, f1, f2, f3;
        asm("mov.b64 {%0, %1}, %2;" : "=f"(f0), "=f"(f1) : "l"(acc[r][0]));
        asm("mov.b64 {%0, %1}, %2;" : "=f"(f2), "=f"(f3) : "l"(acc[r][1]));
        float* dst = P + (size_t)(split * BATCH + 4 * ty + r) * N + j0 + 4 * tx;
        *reinterpret_cast<float4*>(dst) = make_float4(f0, f1, f2, f3);
    }
}

// =====================================================================
// Gaussian pseudo-attention: one warp per (b,i), streams K/V (256 MB)
// with all 16 row loads batched up front (MLP=16). Folds mu/sigma
// split-K combine; accumulates LN(x) stats via atomics.
// =====================================================================
__global__ __launch_bounds__(256)
void gauss_kernel(const float* __restrict__ Kp,
                  const float* __restrict__ Vp,
                  const float* __restrict__ Qp,
                  const float* __restrict__ mu_b,
                  const float* __restrict__ sig_b)
{
    const int tid  = threadIdx.x;
    const int w    = blockIdx.x * 8 + (tid >> 5);
    const int lane = tid & 31;
    const int b = w >> 10;
    const int i = w & 1023;

    float mu = mu_b[i];
    float sg = sig_b[i];
    #pragma unroll
    for (int s = 0; s < MS_SPLIT; ++s) {
        mu += g_part[MU_OFF  + (s * BATCH + b) * NTOK + i];
        sg += g_part[SIG_OFF + (s * BATCH + b) * NTOK + i];
    }
    mu = tanhf(mu);
    const float coef = -0.5f / (sg * sg + 1e-8f);

    const float4* K4 = reinterpret_cast<const float4*>(Kp) + (size_t)w * (DDIM / 4);
    const float4* V4 = reinterpret_cast<const float4*>(Vp) + (size_t)w * (DDIM / 4);

    float4 kr[8], vr[8];
    #pragma unroll
    for (int it = 0; it < 8; ++it) kr[it] = __ldcs(&K4[it * 32 + lane]);
    #pragma unroll
    for (int it = 0; it < 8; ++it) vr[it] = __ldcs(&V4[it * 32 + lane]);

    float acc = 0.f;
    #pragma unroll
    for (int it = 0; it < 8; ++it) {
        float d;
        d = kr[it].x - mu; acc += __expf(coef * d * d) * vr[it].x;
        d = kr[it].y - mu; acc += __expf(coef * d * d) * vr[it].y;
        d = kr[it].z - mu; acc += __expf(coef * d * d) * vr[it].z;
        d = kr[it].w - mu; acc += __expf(coef * d * d) * vr[it].w;
    }
    #pragma unroll
    for (int o = 16; o; o >>= 1) acc += __shfl_xor_sync(0xffffffffu, acc, o);

    __shared__ float shv[8];
    if (lane == 0) {
        const float v = acc + Qp[w];
        g_x[w] = v;
        shv[tid >> 5] = v;
    }
    __syncthreads();
    if (tid < 32) {
        float v = (lane < 8) ? shv[lane] : 0.f;
        float s = v, ss = v * v;
        #pragma unroll
        for (int o = 4; o; o >>= 1) {
            s  += __shfl_xor_sync(0xffffffffu, s,  o);
            ss += __shfl_xor_sync(0xffffffffu, ss, o);
        }
        if (lane == 0) {
            atomicAdd(&g_xraw[2 * b],     s);
            atomicAdd(&g_xraw[2 * b + 1], ss);
        }
    }
}

// =====================================================================
// final combine: out = x + b2 + sum of F2_SPLIT partials   (32 x 1024)
// =====================================================================
__global__ void final_kernel(const float* __restrict__ b2,
                             float* __restrict__ out)
{
    const int t  = blockIdx.x * blockDim.x + threadIdx.x;   // 0..8191 float4s
    const int m  = t >> 8;
    const int j4 = t & 255;
    float4 s = reinterpret_cast<const float4*>(g_x)[t];
    const float4 bb = reinterpret_cast<const float4*>(b2)[j4];
    s.x += bb.x; s.y += bb.y; s.z += bb.z; s.w += bb.w;
    #pragma unroll
    for (int sp = 0; sp < F2_SPLIT; ++sp) {
        const float4 p = *reinterpret_cast<const float4*>(
            g_part + W2_OFF + (size_t)(sp * BATCH + m) * NTOK + j4 * 4);
        s.x += p.x; s.y += p.y; s.z += p.z; s.w += p.w;
    }
    reinterpret_cast<float4*>(out)[t] = s;
}

// =====================================================================
extern "C" void kernel_launch(void* const* d_in, const int* in_sizes, int n_in,
                              void* d_out, int out_size)
{
    const float* Q       = (const float*)d_in[0];
    const float* Kt      = (const float*)d_in[1];
    const float* Vt      = (const float*)d_in[2];
    const float* mu_w    = (const float*)d_in[3];
    const float* mu_b    = (const float*)d_in[4];
    const float* sigma_w = (const float*)d_in[5];
    const float* sigma_b = (const float*)d_in[6];
    const float* ffn_w1  = (const float*)d_in[7];
    const float* ffn_b1  = (const float*)d_in[8];
    const float* ffn_w2  = (const float*)d_in[9];
    const float* ffn_b2  = (const float*)d_in[10];
    const float* ln_ff_g = (const float*)d_in[11];
    const float* ln_ff_b = (const float*)d_in[12];
    const float* ln_q_g  = (const float*)d_in[13];
    const float* ln_q_b  = (const float*)d_in[14];
    float* out = (float*)d_out;

    cudaFuncSetAttribute(gemm_kernel<0>,
                         cudaFuncAttributeMaxDynamicSharedMemorySize, GEMM_SMEM);
    cudaFuncSetAttribute(gemm_kernel<1>,
                         cudaFuncAttributeMaxDynamicSharedMemorySize, GEMM_SMEM);
    cudaFuncSetAttribute(gemm_kernel<2>,
                         cudaFuncAttributeMaxDynamicSharedMemorySize, GEMM_SMEM);

    // 1. Q row stats + zero x-stat accumulators
    stats_kernel<<<1, 1024>>>(Q);

    // 2. mu & sigma partial GEMMs on LN(Q), split-K 16, z selects matrix
    gemm_kernel<0><<<dim3(NTOK / 128, MS_SPLIT, 2), 256, GEMM_SMEM>>>(
        mu_w, sigma_w, NTOK, NTOK, MU_OFF, SIG_OFF - MU_OFF,
        Q, ln_q_g, ln_q_b, nullptr);

    // 3. Gaussian stream + mu/sigma combine + x-stat atomics
    gauss_kernel<<<(BATCH * NTOK) / 8, 256>>>(Kt, Vt, Q, mu_b, sigma_b);

    // 4. FFN GEMM 1 on LN(g_x), split-K 16 -> 512 blocks
    gemm_kernel<1><<<dim3(MFF / 128, F1_SPLIT, 1), 256, GEMM_SMEM>>>(
        ffn_w1, ffn_w1, NTOK, MFF, W1_OFF, 0,
        nullptr, ln_ff_g, ln_ff_b, nullptr);

    // 5. FFN GEMM 2 on silu(partials + b1), split-K 64 -> 512 blocks
    gemm_kernel<2><<<dim3(NTOK / 128, F2_SPLIT, 1), 256, GEMM_SMEM>>>(
        ffn_w2, ffn_w2, MFF, NTOK, W2_OFF, 0,
        nullptr, nullptr, nullptr, ffn_b1);

    // 6. out = x + b2 + sum of FFN2 partials
    final_kernel<<<64, 128>>>(ffn_b2, out);
}

// round 10
// speedup vs baseline: 1.1578x; 1.1578x over previous
#include <cuda_runtime.h>
#include <cstdint>

// ---------------- problem constants ----------------
#define BATCH   32
#define NTOK    1024
#define DDIM    1024
#define MFF     4096
#define LN_EPS  1e-5f

#define MS_SPLIT 16
#define F1_SPLIT 16
#define F2_SPLIT 64

// ---------------- scratch ----------------
__device__ float g_x    [BATCH * NTOK];
__device__ float g_qstat[64];                 // (mean, rstd) per Q row
__device__ float g_xraw [64];                 // (sum, sumsq) per x row (atomics)
__device__ float g_part [4194304];            // split-K partials (16 MB)

#define MU_OFF  0                             // 16*32*1024 = 524288
#define SIG_OFF 524288
#define W1_OFF  0                             // 16*32*4096 = 2097152 (reuses mu/sig)
#define W2_OFF  2097152                       // 64*32*1024 = 2097152

// dynamic smem: W [256][68] + A [32][68], both k-major
#define GEMM_SMEM ((256 * 68 + 32 * 68) * 4)  // 78336 B -> 2 blocks/SM

__device__ __forceinline__ uint32_t smem_u32(const void* p)
{
    return (uint32_t)__cvta_generic_to_shared(p);
}
#define CP_ASYNC16(dst, src) \
    asm volatile("cp.async.ca.shared.global [%0], [%1], 16;\n" \
                 :: "r"(dst), "l"(src))

// =====================================================================
// Q row stats (mean, rstd) + zero the x-stat accumulators. 1 block.
// =====================================================================
__global__ void stats_kernel(const float* __restrict__ Q)
{
    const int tid = threadIdx.x;
    if (tid < 64) g_xraw[tid] = 0.f;
    const int r = tid >> 5, lane = tid & 31;
    const float4* p = reinterpret_cast<const float4*>(Q + r * NTOK);
    float s = 0.f, ss = 0.f;
    #pragma unroll
    for (int i = 0; i < 8; ++i) {
        float4 v = p[lane + 32 * i];
        s  += v.x + v.y + v.z + v.w;
        ss += v.x*v.x + v.y*v.y + v.z*v.z + v.w*v.w;
    }
    #pragma unroll
    for (int o = 16; o; o >>= 1) {
        s  += __shfl_xor_sync(0xffffffffu, s,  o);
        ss += __shfl_xor_sync(0xffffffffu, ss, o);
    }
    if (lane == 0) {
        const float mean = s * (1.0f / NTOK);
        const float var  = ss * (1.0f / NTOK) - mean * mean;
        g_qstat[2 * r]     = mean;
        g_qstat[2 * r + 1] = rsqrtf(var + LN_EPS);
    }
}

// =====================================================================
// Split-K GEMM, k-pair-packed FFMA2 (acc = (sum even k, sum odd k)).
// Block tile 32(M) x 256(N); K strip 64; 256 threads; thread tile
// 8m x 4n (n strided by 64 for conflict-free LDS). Both panels k-major,
// rows padded to 68 floats (17 x 16B, odd -> conflict-free).
// W fetched by cp.async in two 32-k chunks (double-buffered against the
// A-panel build + first compute chunk). Inner loop per k-quad:
// 4 LDS.128 (W) + 8 broadcast LDS.128 (A) + 64 fma.f32x2 -> fma-bound.
// AMODE 0: A = LN(Q) (g_qstat)  1: A = LN(g_x) (g_xraw)
// AMODE 2: A = silu(sum of F1_SPLIT partials + b1)
// gridDim = (N/256, nsplit, nz); z selects W0/W1 (mu/sigma fusion).
// =====================================================================
template<int AMODE>
__global__ __launch_bounds__(256, 2)
void gemm_kernel(const float* __restrict__ W0, const float* __restrict__ W1,
                 int ldw, int N, int partOff, int partStrideZ,
                 const float* __restrict__ Ain,
                 const float* __restrict__ lng, const float* __restrict__ lnb,
                 const float* __restrict__ b1)
{
    extern __shared__ __align__(16) float smem[];
    float* w_s = smem;              // [256 n][68] k-major
    float* a_s = smem + 256 * 68;   // [32 m][68]  k-major

    const int tid = threadIdx.x;
    const float* __restrict__ W = (blockIdx.z == 0) ? W0 : W1;
    float* __restrict__ P = g_part + partOff + (size_t)blockIdx.z * partStrideZ;

    const int j0    = blockIdx.x * 256;
    const int split = blockIdx.y;
    const int kOff  = split * 64;

    // ---- async W fetch: 2 chunks x 8 quads/thread, coalesced ----
    const uint32_t wbase = smem_u32(w_s);
    #pragma unroll
    for (int c = 0; c < 2; ++c) {
        #pragma unroll
        for (int j = 0; j < 8; ++j) {
            const int idx = j * 256 + tid;
            const int n   = idx >> 3;
            const int kq  = (idx & 7) + c * 8;
            const float* src = W + (size_t)(j0 + n) * ldw + kOff + kq * 4;
            CP_ASYNC16(wbase + (uint32_t)((n * 68 + kq * 4) * 4), src);
        }
        asm volatile("cp.async.commit_group;\n");
    }

    // ---- A panel build (overlaps with W in flight): 2 quads/thread ----
    #pragma unroll
    for (int t = 0; t < 2; ++t) {
        const int idx = t * 256 + tid;
        const int ra  = idx >> 4;          // 0..31
        const int kq  = idx & 15;
        const int kc  = kOff + kq * 4;
        float4 av;
        if (AMODE < 2) {
            float mean, rs;
            if (AMODE == 0) { mean = g_qstat[2 * ra]; rs = g_qstat[2 * ra + 1]; }
            else {
                const float s  = g_xraw[2 * ra];
                const float ss = g_xraw[2 * ra + 1];
                mean = s * (1.0f / NTOK);
                rs   = rsqrtf(ss * (1.0f / NTOK) - mean * mean + LN_EPS);
            }
            const float* Arow = (AMODE == 1) ? (g_x + ra * NTOK) : (Ain + ra * NTOK);
            const float4 fa = *reinterpret_cast<const float4*>(Arow + kc);
            const float4 fg = *reinterpret_cast<const float4*>(lng + kc);
            const float4 fb = *reinterpret_cast<const float4*>(lnb + kc);
            av.x = (fa.x - mean) * rs * fg.x + fb.x;
            av.y = (fa.y - mean) * rs * fg.y + fb.y;
            av.z = (fa.z - mean) * rs * fg.z + fb.z;
            av.w = (fa.w - mean) * rs * fg.w + fb.w;
        } else {
            float4 v = *reinterpret_cast<const float4*>(b1 + kc);
            #pragma unroll
            for (int s = 0; s < F1_SPLIT; ++s) {
                const float4 p = *reinterpret_cast<const float4*>(
                    g_part + W1_OFF + (size_t)(s * BATCH + ra) * MFF + kc);
                v.x += p.x; v.y += p.y; v.z += p.z; v.w += p.w;
            }
            av.x = v.x / (1.0f + __expf(-v.x));
            av.y = v.y / (1.0f + __expf(-v.y));
            av.z = v.z / (1.0f + __expf(-v.z));
            av.w = v.w / (1.0f + __expf(-v.w));
        }
        *reinterpret_cast<float4*>(&a_s[ra * 68 + kq * 4]) = av;
    }

    // ---- compute ----
    const int tx = tid & 63, ty = tid >> 6;    // n: tx+64*ni, m: 8*ty+mi

    unsigned long long acc[8][4];
    #pragma unroll
    for (int mi = 0; mi < 8; ++mi)
        #pragma unroll
        for (int ni = 0; ni < 4; ++ni) acc[mi][ni] = 0ull;

    #pragma unroll
    for (int half = 0; half < 2; ++half) {
        if (half == 0) asm volatile("cp.async.wait_group 1;\n");
        else           asm volatile("cp.async.wait_group 0;\n");
        __syncthreads();
        #pragma unroll
        for (int kq = half * 8; kq < half * 8 + 8; ++kq) {
            ulonglong2 wv[4];
            #pragma unroll
            for (int ni = 0; ni < 4; ++ni)
                wv[ni] = *reinterpret_cast<const ulonglong2*>(
                    &w_s[(tx + 64 * ni) * 68 + kq * 4]);
            #pragma unroll
            for (int mi = 0; mi < 8; ++mi) {
                const ulonglong2 avv = *reinterpret_cast<const ulonglong2*>(
                    &a_s[(8 * ty + mi) * 68 + kq * 4]);
                #pragma unroll
                for (int ni = 0; ni < 4; ++ni) {
                    asm("fma.rn.f32x2 %0, %1, %2, %0;"
                        : "+l"(acc[mi][ni]) : "l"(avv.x), "l"(wv[ni].x));
                    asm("fma.rn.f32x2 %0, %1, %2, %0;"
                        : "+l"(acc[mi][ni]) : "l"(avv.y), "l"(wv[ni].y));
                }
            }
        }
    }

    // ---- epilogue: fold (even,odd) pair; m = 8ty+mi, n = j0+tx+64ni ----
    #pragma unroll
    for (int mi = 0; mi < 8; ++mi) {
        float* dst = P + (size_t)(split * BATCH + 8 * ty + mi) * N + j0;
        #pragma unroll
        for (int ni = 0; ni < 4; ++ni) {
            float lo, hi;
            asm("mov.b64 {%0, %1}, %2;" : "=f"(lo), "=f"(hi) : "l"(acc[mi][ni]));
            dst[tx + 64 * ni] = lo + hi;
        }
    }
}

// =====================================================================
// Gaussian pseudo-attention: one warp per (b,i), streams K/V (256 MB)
// with all 16 row loads batched up front (MLP=16). Folds mu/sigma
// split-K combine; accumulates LN(x) stats via atomics.
// =====================================================================
__global__ __launch_bounds__(256)
void gauss_kernel(const float* __restrict__ Kp,
                  const float* __restrict__ Vp,
                  const float* __restrict__ Qp,
                  const float* __restrict__ mu_b,
                  const float* __restrict__ sig_b)
{
    const int tid  = threadIdx.x;
    const int w    = blockIdx.x * 8 + (tid >> 5);
    const int lane = tid & 31;
    const int b = w >> 10;
    const int i = w & 1023;

    float mu = mu_b[i];
    float sg = sig_b[i];
    #pragma unroll
    for (int s = 0; s < MS_SPLIT; ++s) {
        mu += g_part[MU_OFF  + (s * BATCH + b) * NTOK + i];
        sg += g_part[SIG_OFF + (s * BATCH + b) * NTOK + i];
    }
    mu = tanhf(mu);
    const float coef = -0.5f / (sg * sg + 1e-8f);

    const float4* K4 = reinterpret_cast<const float4*>(Kp) + (size_t)w * (DDIM / 4);
    const float4* V4 = reinterpret_cast<const float4*>(Vp) + (size_t)w * (DDIM / 4);

    float4 kr[8], vr[8];
    #pragma unroll
    for (int it = 0; it < 8; ++it) kr[it] = __ldcs(&K4[it * 32 + lane]);
    #pragma unroll
    for (int it = 0; it < 8; ++it) vr[it] = __ldcs(&V4[it * 32 + lane]);

    float acc = 0.f;
    #pragma unroll
    for (int it = 0; it < 8; ++it) {
        float d;
        d = kr[it].x - mu; acc += __expf(coef * d * d) * vr[it].x;
        d = kr[it].y - mu; acc += __expf(coef * d * d) * vr[it].y;
        d = kr[it].z - mu; acc += __expf(coef * d * d) * vr[it].z;
        d = kr[it].w - mu; acc += __expf(coef * d * d) * vr[it].w;
    }
    #pragma unroll
    for (int o = 16; o; o >>= 1) acc += __shfl_xor_sync(0xffffffffu, acc, o);

    __shared__ float shv[8];
    if (lane == 0) {
        const float v = acc + Qp[w];
        g_x[w] = v;
        shv[tid >> 5] = v;
    }
    __syncthreads();
    if (tid < 32) {
        float v = (lane < 8) ? shv[lane] : 0.f;
        float s = v, ss = v * v;
        #pragma unroll
        for (int o = 4; o; o >>= 1) {
            s  += __shfl_xor_sync(0xffffffffu, s,  o);
            ss += __shfl_xor_sync(0xffffffffu, ss, o);
        }
        if (lane == 0) {
            atomicAdd(&g_xraw[2 * b],     s);
            atomicAdd(&g_xraw[2 * b + 1], ss);
        }
    }
}

// =====================================================================
// final combine: out = x + b2 + sum of F2_SPLIT partials   (32 x 1024)
// =====================================================================
__global__ void final_kernel(const float* __restrict__ b2,
                             float* __restrict__ out)
{
    const int t  = blockIdx.x * blockDim.x + threadIdx.x;   // 0..8191 float4s
    const int m  = t >> 8;
    const int j4 = t & 255;
    float4 s = reinterpret_cast<const float4*>(g_x)[t];
    const float4 bb = reinterpret_cast<const float4*>(b2)[j4];
    s.x += bb.x; s.y += bb.y; s.z += bb.z; s.w += bb.w;
    #pragma unroll
    for (int sp = 0; sp < F2_SPLIT; ++sp) {
        const float4 p = *reinterpret_cast<const float4*>(
            g_part + W2_OFF + (size_t)(sp * BATCH + m) * NTOK + j4 * 4);
        s.x += p.x; s.y += p.y; s.z += p.z; s.w += p.w;
    }
    reinterpret_cast<float4*>(out)[t] = s;
}

// =====================================================================
extern "C" void kernel_launch(void* const* d_in, const int* in_sizes, int n_in,
                              void* d_out, int out_size)
{
    const float* Q       = (const float*)d_in[0];
    const float* Kt      = (const float*)d_in[1];
    const float* Vt      = (const float*)d_in[2];
    const float* mu_w    = (const float*)d_in[3];
    const float* mu_b    = (const float*)d_in[4];
    const float* sigma_w = (const float*)d_in[5];
    const float* sigma_b = (const float*)d_in[6];
    const float* ffn_w1  = (const float*)d_in[7];
    const float* ffn_b1  = (const float*)d_in[8];
    const float* ffn_w2  = (const float*)d_in[9];
    const float* ffn_b2  = (const float*)d_in[10];
    const float* ln_ff_g = (const float*)d_in[11];
    const float* ln_ff_b = (const float*)d_in[12];
    const float* ln_q_g  = (const float*)d_in[13];
    const float* ln_q_b  = (const float*)d_in[14];
    float* out = (float*)d_out;

    cudaFuncSetAttribute(gemm_kernel<0>,
                         cudaFuncAttributeMaxDynamicSharedMemorySize, GEMM_SMEM);
    cudaFuncSetAttribute(gemm_kernel<1>,
                         cudaFuncAttributeMaxDynamicSharedMemorySize, GEMM_SMEM);
    cudaFuncSetAttribute(gemm_kernel<2>,
                         cudaFuncAttributeMaxDynamicSharedMemorySize, GEMM_SMEM);

    // 1. Q row stats + zero x-stat accumulators
    stats_kernel<<<1, 1024>>>(Q);

    // 2. mu & sigma partial GEMMs on LN(Q), split-K 16, z selects matrix
    gemm_kernel<0><<<dim3(NTOK / 256, MS_SPLIT, 2), 256, GEMM_SMEM>>>(
        mu_w, sigma_w, NTOK, NTOK, MU_OFF, SIG_OFF - MU_OFF,
        Q, ln_q_g, ln_q_b, nullptr);

    // 3. Gaussian stream + mu/sigma combine + x-stat atomics
    gauss_kernel<<<(BATCH * NTOK) / 8, 256>>>(Kt, Vt, Q, mu_b, sigma_b);

    // 4. FFN GEMM 1 on LN(g_x), split-K 16 -> 256 blocks
    gemm_kernel<1><<<dim3(MFF / 256, F1_SPLIT, 1), 256, GEMM_SMEM>>>(
        ffn_w1, ffn_w1, NTOK, MFF, W1_OFF, 0,
        nullptr, ln_ff_g, ln_ff_b, nullptr);

    // 5. FFN GEMM 2 on silu(partials + b1), split-K 64 -> 256 blocks
    gemm_kernel<2><<<dim3(NTOK / 256, F2_SPLIT, 1), 256, GEMM_SMEM>>>(
        ffn_w2, ffn_w2, MFF, NTOK, W2_OFF, 0,
        nullptr, nullptr, nullptr, ffn_b1);

    // 6. out = x + b2 + sum of FFN2 partials
    final_kernel<<<64, 128>>>(ffn_b2, out);
}